// round 9
// baseline (speedup 1.0000x reference)
#include <cuda_runtime.h>
#include <math.h>
#include <stdint.h>

#define BB 128
#define TT 1024
#define DD 43
#define HH 256
#define G4 1024

// ---- static device scratch (allocation-free) ----
__device__ float g_xg[(size_t)TT * BB * G4];   // [t][b][g]
__device__ float g_hs[(size_t)BB * TT * HH];   // [b][t][k]
__device__ float g_a1[(size_t)BB * TT * HH];   // [tok][k]

__device__ __forceinline__ float sigf(float x) {
    float y;
    asm("tanh.approx.f32 %0, %1;" : "=f"(y) : "f"(0.5f * x));
    return 0.5f * y + 0.5f;
}
__device__ __forceinline__ float tanhf_fast(float x) {
    float y;
    asm("tanh.approx.f32 %0, %1;" : "=f"(y) : "f"(x));
    return y;
}

#define PACK2(d, lo, hi)   asm("mov.b64 %0, {%1, %2};" : "=l"(d) : "f"(lo), "f"(hi))
#define DUP2(d, s)         asm("mov.b64 %0, {%1, %1};" : "=l"(d) : "f"(s))
#define UNPACK2(lo, hi, s) asm("mov.b64 {%0, %1}, %2;" : "=f"(lo), "=f"(hi) : "l"(s))
#define FFMA2(acc, a, b)   asm("fma.rn.f32x2 %0, %1, %2, %0;" : "+l"(acc) : "l"(a), "l"(b))

// ---------------------------------------------------------------------------
// Kernel A: xg[t][b][g] = xin[b,t,:] . W_ih[g,:] + b_ih[g] + b_hh[g]
// ---------------------------------------------------------------------------
__global__ void __launch_bounds__(256) kA(const float* __restrict__ x,
                                          const float* __restrict__ Wih,
                                          const float* __restrict__ bih,
                                          const float* __restrict__ bhh) {
    __shared__ float xin[32 * 44];
    const int tid = threadIdx.x;
    const int g0  = blockIdx.x * 256;
    const int t0  = blockIdx.y * 32;
    const int b   = blockIdx.z;

    for (int e = tid; e < 32 * 44; e += 256) {
        int tt = e / 44, d = e % 44;
        int t = t0 + tt;
        float v = 0.0f;
        if (d < 35)      v = x[((size_t)b * TT + t) * DD + d];
        else if (d < 43) { if (t > 0) v = x[((size_t)b * TT + t - 1) * DD + d]; }
        xin[e] = v;
    }

    const int g = g0 + tid;
    float w[44];
#pragma unroll
    for (int d = 0; d < 43; d++) w[d] = Wih[g * DD + d];
    w[43] = 0.0f;
    const float bias = bih[g] + bhh[g];
    __syncthreads();

#pragma unroll 4
    for (int tt = 0; tt < 32; tt++) {
        const float* xr = &xin[tt * 44];
        float acc = bias;
#pragma unroll
        for (int d = 0; d < 44; d++) acc += w[d] * xr[d];
        g_xg[((size_t)(t0 + tt) * BB + b) * G4 + g] = acc;
    }
}

// ---------------------------------------------------------------------------
// Kernel B: persistent LSTM. Clusters of 8 CTAs = one batch-group.
// hsl = rank = hidden slice. h exchanged via DSMEM (st.shared::cluster) into
// double-buffered smem; per-step sync via cluster mbarrier release/acquire.
// ---------------------------------------------------------------------------
#define WSTR   260
#define HB     (256 * 8)                       // floats per h buffer
#define HBUF_OFF (128 * WSTR)                  // float index of hbuf[0]
#define GSH_OFF  (HBUF_OFF + 2 * HB)           // float index of gsh
#define MBAR_OFF_B ((GSH_OFF + 128 * 9) * 4)   // byte offset of mbarrier (16B aligned)
#define SMEM_B   (MBAR_OFF_B + 16)

__device__ __forceinline__ uint32_t smem_u32(const void* p) {
    uint32_t a;
    asm("{ .reg .u64 t; cvta.to.shared.u64 t, %1; cvt.u32.u64 %0, t; }" : "=r"(a) : "l"(p));
    return a;
}

__global__ void __launch_bounds__(256, 1) __cluster_dims__(8, 1, 1)
kB(const float* __restrict__ Whh) {
    extern __shared__ float sm[];
    float* Wsh  = sm;                    // [128][260]
    float* hbuf = sm + HBUF_OFF;         // [2][256][8]  (k-major, batch minor)
    float* gsh  = sm + GSH_OFF;          // [128][9]     raw gates

    const int tid = threadIdx.x;
    const int cta = blockIdx.x;
    const int bg  = cta >> 3;            // batch group 0..15
    const int hsl = cta & 7;             // hidden slice = cluster rank
    const int b0  = bg * 8;

    const uint32_t smb      = smem_u32(sm);
    const uint32_t mbar     = smb + MBAR_OFF_B;

    // one-time init: mbarrier (8 arrivals per phase) + zero hbuf[1] (h(-1)=0)
    if (tid == 0) {
        asm volatile("mbarrier.init.shared.b64 [%0], %1;" :: "r"(mbar), "r"(8) : "memory");
    }
    for (int e = tid; e < HB; e += 256) hbuf[HB + e] = 0.0f;

    // load W_hh slice: local row r -> global row (r>>5)*256 + hsl*32 + (r&31)
    for (int e = tid; e < 128 * 256; e += 256) {
        int r = e >> 8, k = e & 255;
        int R = ((r >> 5) << 8) + hsl * 32 + (r & 31);
        Wsh[r * WSTR + k] = Whh[R * 256 + k];
    }
    __syncthreads();
    asm volatile("barrier.cluster.arrive.aligned;" ::: "memory");
    asm volatile("barrier.cluster.wait.aligned;" ::: "memory");

    // compute-thread mapping
    const int r  = tid >> 1;             // gate row 0..127
    const int bh = tid & 1;              // batch half (4 batches each)
    const int R  = ((r >> 5) << 8) + hsl * 32 + (r & 31);
    // update-thread mapping
    const int ub = tid >> 5;             // batch 0..7
    const int uk = tid & 31;             // local hidden 0..31

    // DSMEM destination addresses for this thread's h slot in every peer's buf0
    uint32_t dsm[8];
    {
        uint32_t la = smb + (HBUF_OFF + ((hsl * 32 + uk) * 8 + ub)) * 4;
#pragma unroll
        for (int p = 0; p < 8; p++) {
            asm("mapa.shared::cluster.u32 %0, %1, %2;" : "=r"(dsm[p]) : "r"(la), "r"(p));
        }
    }
    // remote mbarrier address for arriving thread (tid < 8)
    uint32_t rmbar = 0;
    if (tid < 8)
        asm("mapa.shared::cluster.u32 %0, %1, %2;" : "=r"(rmbar) : "r"(mbar), "r"(tid));

    float c = 0.0f;

    // prefetch xg for t=0
    float px0, px1, px2, px3;
    {
        const float* p = &g_xg[((size_t)b0 + bh * 4) * G4 + R];
        px0 = __ldcg(p); px1 = __ldcg(p + G4);
        px2 = __ldcg(p + 2 * G4); px3 = __ldcg(p + 3 * G4);
    }

    for (int t = 0; t < TT; t++) {
        // ---- gates = xg + W.h  (packed f32x2, pairs over batches) ----
        {
            unsigned long long p01, p23;
            PACK2(p01, px0, px1);
            PACK2(p23, px2, px3);
            // prefetch next step's xg immediately: ~full step of latency cover
            {
                int tn = (t + 1 < TT) ? (t + 1) : t;
                const float* p = &g_xg[((size_t)tn * BB + b0 + bh * 4) * G4 + R];
                px0 = __ldcg(p); px1 = __ldcg(p + G4);
                px2 = __ldcg(p + 2 * G4); px3 = __ldcg(p + 3 * G4);
            }
            const float4* wp = (const float4*)&Wsh[r * WSTR];
            const ulonglong2* hq =
                (const ulonglong2*)(hbuf + ((t + 1) & 1) * HB);   // h(t-1)
#pragma unroll 8
            for (int k4 = 0; k4 < 64; k4++) {
                float4 w4 = wp[k4];
                ulonglong2 hA = hq[(4 * k4 + 0) * 2 + bh];
                ulonglong2 hB = hq[(4 * k4 + 1) * 2 + bh];
                ulonglong2 hC = hq[(4 * k4 + 2) * 2 + bh];
                ulonglong2 hD = hq[(4 * k4 + 3) * 2 + bh];
                unsigned long long w2;
                DUP2(w2, w4.x);
                FFMA2(p01, w2, hA.x); FFMA2(p23, w2, hA.y);
                DUP2(w2, w4.y);
                FFMA2(p01, w2, hB.x); FFMA2(p23, w2, hB.y);
                DUP2(w2, w4.z);
                FFMA2(p01, w2, hC.x); FFMA2(p23, w2, hC.y);
                DUP2(w2, w4.w);
                FFMA2(p01, w2, hD.x); FFMA2(p23, w2, hD.y);
            }
            float a0, a1, a2, a3;
            UNPACK2(a0, a1, p01);
            UNPACK2(a2, a3, p23);
            float* gp = &gsh[r * 9 + bh * 4];
            gp[0] = a0; gp[1] = a1; gp[2] = a2; gp[3] = a3;
        }
        __syncthreads();

        // ---- pointwise LSTM update + DSMEM broadcast of h(t) ----
        {
            float gi = sigf(      gsh[(uk)      * 9 + ub]);
            float gf = sigf(      gsh[(32 + uk) * 9 + ub]);
            float gg = tanhf_fast(gsh[(64 + uk) * 9 + ub]);
            float go = sigf(      gsh[(96 + uk) * 9 + ub]);
            c = gf * c + gi * gg;
            float h = go * tanhf_fast(c);
            g_hs[(((size_t)(b0 + ub)) * TT + t) * HH + hsl * 32 + uk] = h;
            if (t + 1 < TT) {
                const uint32_t off = (uint32_t)(t & 1) * (HB * 4);
#pragma unroll
                for (int p = 0; p < 8; p++)
                    asm volatile("st.shared::cluster.f32 [%0], %1;"
                                 :: "r"(dsm[p] + off), "f"(h) : "memory");
            }
        }
        __syncthreads();                 // all h stores + gsh reads done

        if (t + 1 < TT) {
            // release-arrive on every peer's mbarrier (threads 0..7, one each)
            if (tid < 8)
                asm volatile("mbarrier.arrive.release.cluster.shared::cluster.b64 _, [%0];"
                             :: "r"(rmbar) : "memory");
            // acquire-wait on local mbarrier: all 8 slices' h(t) present
            {
                const uint32_t parity = (uint32_t)(t & 1);
                uint32_t done;
                asm volatile(
                    "{\n\t.reg .pred p;\n\t"
                    "mbarrier.try_wait.parity.acquire.cluster.shared::cta.b64 p, [%1], %2;\n\t"
                    "selp.b32 %0, 1, 0, p;\n\t}"
                    : "=r"(done) : "r"(mbar), "r"(parity) : "memory");
                if (!done) {
                    asm volatile(
                        "{\n\t.reg .pred P1;\n\t"
                        "WAIT_B_%=:\n\t"
                        "mbarrier.try_wait.parity.acquire.cluster.shared::cta.b64 P1, [%0], %1, 0x989680;\n\t"
                        "@P1 bra.uni DONE_B_%=;\n\t"
                        "bra.uni WAIT_B_%=;\n\t"
                        "DONE_B_%=:\n\t}"
                        :: "r"(mbar), "r"(parity) : "memory");
                }
            }
        }
    }
}

// ---------------------------------------------------------------------------
// Kernel C1: a1 = relu(hs @ W_afc1^T + b).  Block: 32 tokens x 256 outputs.
// ---------------------------------------------------------------------------
#define SMEM_C1 ((32 * 256 + 256 * 68) * 4)

__global__ void __launch_bounds__(256) kC1(const float* __restrict__ Wa,
                                           const float* __restrict__ ba) {
    extern __shared__ float sm[];
    float* hsh = sm;               // [32][256]
    float* Ws  = sm + 32 * 256;    // [256][68] current K-chunk

    const int tid  = threadIdx.x;
    const int tok0 = blockIdx.x * 32;

    for (int e = tid; e < 32 * 256; e += 256)
        hsh[e] = g_hs[(size_t)tok0 * 256 + e];

    float acc[32];
    const float bias = ba[tid];
#pragma unroll
    for (int i = 0; i < 32; i++) acc[i] = bias;

    for (int kc = 0; kc < 4; kc++) {
        __syncthreads();
        for (int e = tid; e < 256 * 64; e += 256) {
            int j = e >> 6, kk = e & 63;
            Ws[j * 68 + kk] = Wa[j * 256 + kc * 64 + kk];
        }
        __syncthreads();
        const float4* wp = (const float4*)&Ws[tid * 68];
#pragma unroll
        for (int q = 0; q < 16; q++) {
            float4 w4 = wp[q];
            const int kbase = kc * 64 + q * 4;
#pragma unroll 8
            for (int tt = 0; tt < 32; tt++) {
                float4 h = *(const float4*)&hsh[tt * 256 + kbase];
                acc[tt] += w4.x * h.x + w4.y * h.y + w4.z * h.z + w4.w * h.w;
            }
        }
    }
#pragma unroll
    for (int tt = 0; tt < 32; tt++)
        g_a1[((size_t)(tok0 + tt)) * 256 + tid] = fmaxf(acc[tt], 0.0f);
}

// ---------------------------------------------------------------------------
// Kernel C2: cont / bin / act heads.
// ---------------------------------------------------------------------------
#define CONT_BASE 0
#define BIN_BASE  (128 * 1024 * 50)
#define ACT_BASE  (BIN_BASE + 128 * 1024 * 10)
#define SMEM_C2 ((32 * 268 + 32 * 256 + 50 * 268 + 10 * 268 + 8 * 256 + 68) * 4)

__global__ void __launch_bounds__(256) kC2(const float* __restrict__ x,
                                           const float* __restrict__ Wao,
                                           const float* __restrict__ bao,
                                           const float* __restrict__ Wc,
                                           const float* __restrict__ bc,
                                           const float* __restrict__ Wb,
                                           const float* __restrict__ bb,
                                           float* __restrict__ out) {
    extern __shared__ float sm[];
    float* pred = sm;                   // [32][268]  (h | cur)
    float* a1s  = pred + 32 * 268;      // [32][256]
    float* Wcs  = a1s  + 32 * 256;      // [50][268]
    float* Wbs  = Wcs  + 50 * 268;      // [10][268]
    float* Was  = Wbs  + 10 * 268;      // [8][256]
    float* bcs  = Was  + 8 * 256;       // 50
    float* bbs  = bcs + 50;             // 10
    float* bas  = bbs + 10;             // 8

    const int tid  = threadIdx.x;
    const int tok0 = blockIdx.x * 32;

    for (int e = tid; e < 32 * 256; e += 256) {
        int tt = e >> 8, k = e & 255;
        pred[tt * 268 + k] = g_hs[(size_t)tok0 * 256 + e];
        a1s[e]             = g_a1[(size_t)tok0 * 256 + e];
    }
    if (tid < 32 * 8) {
        int tt = tid >> 3, j = tid & 7;
        pred[tt * 268 + 256 + j] = x[((size_t)(tok0 + tt)) * DD + 35 + j];
    }
    for (int e = tid; e < 50 * 264; e += 256) {
        int o = e / 264, d = e % 264;
        Wcs[o * 268 + d] = Wc[e];
    }
    for (int e = tid; e < 10 * 264; e += 256) {
        int o = e / 264, d = e % 264;
        Wbs[o * 268 + d] = Wb[e];
    }
    for (int e = tid; e < 8 * 256; e += 256) Was[e] = Wao[e];
    if (tid < 50) bcs[tid] = bc[tid];
    if (tid < 10) bbs[tid] = bb[tid];
    if (tid < 8)  bas[tid] = bao[tid];
    __syncthreads();

    for (int idx = tid; idx < 32 * 68; idx += 256) {
        const int tt   = idx / 68;
        const int o    = idx % 68;
        const int gtok = tok0 + tt;
        if (o < 50) {
            float acc = bcs[o];
            const float4* wp = (const float4*)&Wcs[o * 268];
            const float4* pp = (const float4*)&pred[tt * 268];
#pragma unroll 11
            for (int q = 0; q < 66; q++) {
                float4 w = wp[q], p = pp[q];
                acc += w.x * p.x + w.y * p.y + w.z * p.z + w.w * p.w;
            }
            out[CONT_BASE + (size_t)gtok * 50 + o] = acc;
        } else if (o < 60) {
            const int o2 = o - 50;
            float acc = bbs[o2];
            const float4* wp = (const float4*)&Wbs[o2 * 268];
            const float4* pp = (const float4*)&pred[tt * 268];
#pragma unroll 11
            for (int q = 0; q < 66; q++) {
                float4 w = wp[q], p = pp[q];
                acc += w.x * p.x + w.y * p.y + w.z * p.z + w.w * p.w;
            }
            out[BIN_BASE + (size_t)gtok * 10 + o2] = 1.0f / (1.0f + __expf(-acc));
        } else {
            const int o3 = o - 60;
            float acc = bas[o3];
            const float4* wp = (const float4*)&Was[o3 * 256];
            const float4* pp = (const float4*)&a1s[tt * 256];
#pragma unroll 16
            for (int q = 0; q < 64; q++) {
                float4 w = wp[q], p = pp[q];
                acc += w.x * p.x + w.y * p.y + w.z * p.z + w.w * p.w;
            }
            out[ACT_BASE + (size_t)gtok * 8 + o3] = acc;
        }
    }
}

// ---------------------------------------------------------------------------
extern "C" void kernel_launch(void* const* d_in, const int* in_sizes, int n_in,
                              void* d_out, int out_size) {
    const float* x    = (const float*)d_in[0];
    const float* Wih  = (const float*)d_in[1];
    const float* Whh  = (const float*)d_in[2];
    const float* bih  = (const float*)d_in[3];
    const float* bhh  = (const float*)d_in[4];
    const float* Wafc = (const float*)d_in[5];
    const float* bafc = (const float*)d_in[6];
    const float* Wao  = (const float*)d_in[7];
    const float* bao  = (const float*)d_in[8];
    const float* Wc   = (const float*)d_in[9];
    const float* bc   = (const float*)d_in[10];
    const float* Wb   = (const float*)d_in[11];
    const float* bb   = (const float*)d_in[12];
    float* out = (float*)d_out;

    cudaFuncSetAttribute(kB,  cudaFuncAttributeMaxDynamicSharedMemorySize, SMEM_B);
    cudaFuncSetAttribute(kC1, cudaFuncAttributeMaxDynamicSharedMemorySize, SMEM_C1);
    cudaFuncSetAttribute(kC2, cudaFuncAttributeMaxDynamicSharedMemorySize, SMEM_C2);

    kA<<<dim3(4, 32, 128), 256>>>(x, Wih, bih, bhh);
    kB<<<128, 256, SMEM_B>>>(Whh);
    kC1<<<4096, 256, SMEM_C1>>>(Wafc, bafc);
    kC2<<<4096, 256, SMEM_C2>>>(x, Wao, bao, Wc, bc, Wb, bb, out);
}

// round 10
// speedup vs baseline: 1.8562x; 1.8562x over previous
#include <cuda_runtime.h>
#include <math.h>
#include <stdint.h>

#define BB 128
#define TT 1024
#define DD 43
#define HH 256
#define G4 1024

// ---- static device scratch (allocation-free) ----
__device__ float g_xg[(size_t)TT * BB * G4];   // [t][b][g]
__device__ float g_hs[(size_t)BB * TT * HH];   // [b][t][k]
__device__ float g_a1[(size_t)BB * TT * HH];   // [tok][k]
__device__ int   g_bar[16 * 64];               // padded: one counter per 256B

__device__ __forceinline__ int ld_acquire(const int* p) {
    int v;
    asm volatile("ld.acquire.gpu.global.b32 %0, [%1];" : "=r"(v) : "l"(p));
    return v;
}
__device__ __forceinline__ void red_release_add(int* p, int v) {
    asm volatile("red.release.gpu.global.add.s32 [%0], %1;" :: "l"(p), "r"(v) : "memory");
}
__device__ __forceinline__ float sigf(float x) {
    float y;
    asm("tanh.approx.f32 %0, %1;" : "=f"(y) : "f"(0.5f * x));
    return 0.5f * y + 0.5f;
}
__device__ __forceinline__ float tanhf_fast(float x) {
    float y;
    asm("tanh.approx.f32 %0, %1;" : "=f"(y) : "f"(x));
    return y;
}

#define UNPACK2(lo, hi, s) asm("mov.b64 {%0, %1}, %2;" : "=f"(lo), "=f"(hi) : "l"(s))
#define FFMA2(acc, a, b)   asm("fma.rn.f32x2 %0, %1, %2, %0;" : "+l"(acc) : "l"(a), "l"(b))

// ---------------------------------------------------------------------------
__global__ void k_init() {
    if (threadIdx.x < 16) g_bar[threadIdx.x * 64] = 0;
}

// ---------------------------------------------------------------------------
// Kernel A: xg[t][b][g] = xin[b,t,:] . W_ih[g,:] + b_ih[g] + b_hh[g]
// ---------------------------------------------------------------------------
__global__ void __launch_bounds__(256) kA(const float* __restrict__ x,
                                          const float* __restrict__ Wih,
                                          const float* __restrict__ bih,
                                          const float* __restrict__ bhh) {
    __shared__ float xin[32 * 44];
    const int tid = threadIdx.x;
    const int g0  = blockIdx.x * 256;
    const int t0  = blockIdx.y * 32;
    const int b   = blockIdx.z;

    for (int e = tid; e < 32 * 44; e += 256) {
        int tt = e / 44, d = e % 44;
        int t = t0 + tt;
        float v = 0.0f;
        if (d < 35)      v = x[((size_t)b * TT + t) * DD + d];
        else if (d < 43) { if (t > 0) v = x[((size_t)b * TT + t - 1) * DD + d]; }
        xin[e] = v;
    }

    const int g = g0 + tid;
    float w[44];
#pragma unroll
    for (int d = 0; d < 43; d++) w[d] = Wih[g * DD + d];
    w[43] = 0.0f;
    const float bias = bih[g] + bhh[g];
    __syncthreads();

#pragma unroll 4
    for (int tt = 0; tt < 32; tt++) {
        const float* xr = &xin[tt * 44];
        float acc = bias;
#pragma unroll
        for (int d = 0; d < 44; d++) acc += w[d] * xr[d];
        g_xg[((size_t)(t0 + tt) * BB + b) * G4 + g] = acc;
    }
}

// ---------------------------------------------------------------------------
// Kernel B: persistent LSTM, 128 CTAs = 16 batch-groups x 8 hidden-slices.
// 512 threads: GEMM split over K-halves (kh), f32x2 pairing over K (no DUPs),
// h stored [b][k] transposed in smem. Global-L2 counting barrier per step.
// ---------------------------------------------------------------------------
#define WSTR   260
#define HS_OFF (128 * WSTR)            // hsh: [8][260]
#define GS_OFF (HS_OFF + 8 * WSTR)     // gsh: [2][128*9]
#define SMEM_B ((GS_OFF + 2 * 128 * 9 + 16) * 4)

__global__ void __launch_bounds__(512, 1) kB(const float* __restrict__ Whh) {
    extern __shared__ float sm[];
    float* Wsh = sm;                   // [128][260]
    float* hsh = sm + HS_OFF;          // [8][260]   h(t-1), [batch][k]
    float* gsh = sm + GS_OFF;          // [2][128*9] K-half partial gates

    const int tid = threadIdx.x;
    const int cta = blockIdx.x;
    const int bg  = cta >> 3;          // batch group 0..15
    const int hsl = cta & 7;           // hidden slice 0..7
    const int b0  = bg * 8;

    // load W_hh slice: local row r -> global row (r>>5)*256 + hsl*32 + (r&31)
    for (int e = tid; e < 128 * 256; e += 512) {
        int r = e >> 8, k = e & 255;
        int R = ((r >> 5) << 8) + hsl * 32 + (r & 31);
        Wsh[r * WSTR + k] = Whh[R * 256 + k];
    }

    // GEMM mapping: kh = K-half, r = gate row, bh = batch half (4 batches)
    const int kh  = tid >> 8;
    const int sub = tid & 255;
    const int r   = sub >> 1;
    const int bh  = sub & 1;
    // pointwise mapping (tid < 256)
    const int ub = sub >> 5;           // batch 0..7
    const int uk = sub & 31;           // local hidden 0..31
    // stage mapping
    const int sb = tid >> 6;           // batch 0..7
    const int sk = tid & 63;           // k-quad 0..63

    int* barp = &g_bar[bg * 64];
    float c = 0.0f;

    // h(-1) = 0
    for (int e = tid; e < 8 * WSTR; e += 512) hsh[e] = 0.0f;

    // prefetch xg[0] (pointwise threads)
    float px0, px1, px2, px3;
    if (tid < 256) {
        const float* p = &g_xg[((size_t)b0 + ub) * G4 + hsl * 32 + uk];
        px0 = __ldcg(p);       px1 = __ldcg(p + 256);
        px2 = __ldcg(p + 512); px3 = __ldcg(p + 768);
    }
    __syncthreads();

    for (int t = 0; t < TT; t++) {
        // prefetch next step's xg (covered by GEMM latency)
        float nx0, nx1, nx2, nx3;
        if (tid < 256) {
            int tn = (t + 1 < TT) ? (t + 1) : t;
            const float* p = &g_xg[((size_t)tn * BB + b0 + ub) * G4 + hsl * 32 + uk];
            nx0 = __ldcg(p);       nx1 = __ldcg(p + 256);
            nx2 = __ldcg(p + 512); nx3 = __ldcg(p + 768);
        }

        // ---- GEMM partial: this thread's K-half, 4 batches, f32x2 over K ----
        {
            unsigned long long a0 = 0, a1 = 0, a2 = 0, a3 = 0;
            const ulonglong2* wp = (const ulonglong2*)&Wsh[r * WSTR + kh * 128];
            const ulonglong2* h0 = (const ulonglong2*)&hsh[(bh * 4 + 0) * WSTR + kh * 128];
            const ulonglong2* h1 = (const ulonglong2*)&hsh[(bh * 4 + 1) * WSTR + kh * 128];
            const ulonglong2* h2 = (const ulonglong2*)&hsh[(bh * 4 + 2) * WSTR + kh * 128];
            const ulonglong2* h3 = (const ulonglong2*)&hsh[(bh * 4 + 3) * WSTR + kh * 128];
#pragma unroll 8
            for (int i = 0; i < 32; i++) {
                ulonglong2 w = wp[i];
                ulonglong2 q0 = h0[i];
                FFMA2(a0, w.x, q0.x); FFMA2(a0, w.y, q0.y);
                ulonglong2 q1 = h1[i];
                FFMA2(a1, w.x, q1.x); FFMA2(a1, w.y, q1.y);
                ulonglong2 q2 = h2[i];
                FFMA2(a2, w.x, q2.x); FFMA2(a2, w.y, q2.y);
                ulonglong2 q3 = h3[i];
                FFMA2(a3, w.x, q3.x); FFMA2(a3, w.y, q3.y);
            }
            float lo, hi, s0, s1, s2, s3;
            UNPACK2(lo, hi, a0); s0 = lo + hi;
            UNPACK2(lo, hi, a1); s1 = lo + hi;
            UNPACK2(lo, hi, a2); s2 = lo + hi;
            UNPACK2(lo, hi, a3); s3 = lo + hi;
            float* gp = &gsh[kh * (128 * 9) + r * 9 + bh * 4];
            gp[0] = s0; gp[1] = s1; gp[2] = s2; gp[3] = s3;
        }
        __syncthreads();

        // ---- pointwise LSTM update (tid < 256) ----
        if (tid < 256) {
            float gi = gsh[(uk)      * 9 + ub] + gsh[128 * 9 + (uk)      * 9 + ub] + px0;
            float gf = gsh[(32 + uk) * 9 + ub] + gsh[128 * 9 + (32 + uk) * 9 + ub] + px1;
            float gg = gsh[(64 + uk) * 9 + ub] + gsh[128 * 9 + (64 + uk) * 9 + ub] + px2;
            float go = gsh[(96 + uk) * 9 + ub] + gsh[128 * 9 + (96 + uk) * 9 + ub] + px3;
            gi = sigf(gi); gf = sigf(gf);
            gg = tanhf_fast(gg); go = sigf(go);
            c = gf * c + gi * gg;
            float h = go * tanhf_fast(c);
            g_hs[(((size_t)(b0 + ub)) * TT + t) * HH + hsl * 32 + uk] = h;
            px0 = nx0; px1 = nx1; px2 = nx2; px3 = nx3;
        }

        if (t + 1 < TT) {
            // ---- inter-CTA barrier over the 8 slices of this batch group ----
            __syncthreads();                   // all h STGs ordered before release
            if (tid == 0) {
                red_release_add(barp, 1);
                const int target = 8 * (t + 1);
                while (ld_acquire(barp) < target) { }
            }
            __syncthreads();

            // ---- stage h(t) -> hsh[b][k] (transposed, k-contiguous) ----
            float4 v = __ldcg((const float4*)
                &g_hs[(((size_t)(b0 + sb)) * TT + t) * HH + sk * 4]);
            *(float4*)&hsh[sb * WSTR + sk * 4] = v;
            __syncthreads();
        }
    }
}

// ---------------------------------------------------------------------------
// Kernel C1: a1 = relu(hs @ W_afc1^T + b).  Block: 32 tokens x 256 outputs.
// ---------------------------------------------------------------------------
#define SMEM_C1 ((32 * 256 + 256 * 68) * 4)

__global__ void __launch_bounds__(256) kC1(const float* __restrict__ Wa,
                                           const float* __restrict__ ba) {
    extern __shared__ float sm[];
    float* hsh = sm;               // [32][256]
    float* Ws  = sm + 32 * 256;    // [256][68] current K-chunk

    const int tid  = threadIdx.x;
    const int tok0 = blockIdx.x * 32;

    for (int e = tid; e < 32 * 256; e += 256)
        hsh[e] = g_hs[(size_t)tok0 * 256 + e];

    float acc[32];
    const float bias = ba[tid];
#pragma unroll
    for (int i = 0; i < 32; i++) acc[i] = bias;

    for (int kc = 0; kc < 4; kc++) {
        __syncthreads();
        for (int e = tid; e < 256 * 64; e += 256) {
            int j = e >> 6, kk = e & 63;
            Ws[j * 68 + kk] = Wa[j * 256 + kc * 64 + kk];
        }
        __syncthreads();
        const float4* wp = (const float4*)&Ws[tid * 68];
#pragma unroll
        for (int q = 0; q < 16; q++) {
            float4 w4 = wp[q];
            const int kbase = kc * 64 + q * 4;
#pragma unroll 8
            for (int tt = 0; tt < 32; tt++) {
                float4 h = *(const float4*)&hsh[tt * 256 + kbase];
                acc[tt] += w4.x * h.x + w4.y * h.y + w4.z * h.z + w4.w * h.w;
            }
        }
    }
#pragma unroll
    for (int tt = 0; tt < 32; tt++)
        g_a1[((size_t)(tok0 + tt)) * 256 + tid] = fmaxf(acc[tt], 0.0f);
}

// ---------------------------------------------------------------------------
// Kernel C2: cont / bin / act heads.
// ---------------------------------------------------------------------------
#define CONT_BASE 0
#define BIN_BASE  (128 * 1024 * 50)
#define ACT_BASE  (BIN_BASE + 128 * 1024 * 10)
#define SMEM_C2 ((32 * 268 + 32 * 256 + 50 * 268 + 10 * 268 + 8 * 256 + 68) * 4)

__global__ void __launch_bounds__(256) kC2(const float* __restrict__ x,
                                           const float* __restrict__ Wao,
                                           const float* __restrict__ bao,
                                           const float* __restrict__ Wc,
                                           const float* __restrict__ bc,
                                           const float* __restrict__ Wb,
                                           const float* __restrict__ bb,
                                           float* __restrict__ out) {
    extern __shared__ float sm[];
    float* pred = sm;                   // [32][268]  (h | cur)
    float* a1s  = pred + 32 * 268;      // [32][256]
    float* Wcs  = a1s  + 32 * 256;      // [50][268]
    float* Wbs  = Wcs  + 50 * 268;      // [10][268]
    float* Was  = Wbs  + 10 * 268;      // [8][256]
    float* bcs  = Was  + 8 * 256;       // 50
    float* bbs  = bcs + 50;             // 10
    float* bas  = bbs + 10;             // 8

    const int tid  = threadIdx.x;
    const int tok0 = blockIdx.x * 32;

    for (int e = tid; e < 32 * 256; e += 256) {
        int tt = e >> 8, k = e & 255;
        pred[tt * 268 + k] = g_hs[(size_t)tok0 * 256 + e];
        a1s[e]             = g_a1[(size_t)tok0 * 256 + e];
    }
    if (tid < 32 * 8) {
        int tt = tid >> 3, j = tid & 7;
        pred[tt * 268 + 256 + j] = x[((size_t)(tok0 + tt)) * DD + 35 + j];
    }
    for (int e = tid; e < 50 * 264; e += 256) {
        int o = e / 264, d = e % 264;
        Wcs[o * 268 + d] = Wc[e];
    }
    for (int e = tid; e < 10 * 264; e += 256) {
        int o = e / 264, d = e % 264;
        Wbs[o * 268 + d] = Wb[e];
    }
    for (int e = tid; e < 8 * 256; e += 256) Was[e] = Wao[e];
    if (tid < 50) bcs[tid] = bc[tid];
    if (tid < 10) bbs[tid] = bb[tid];
    if (tid < 8)  bas[tid] = bao[tid];
    __syncthreads();

    for (int idx = tid; idx < 32 * 68; idx += 256) {
        const int tt   = idx / 68;
        const int o    = idx % 68;
        const int gtok = tok0 + tt;
        if (o < 50) {
            float acc = bcs[o];
            const float4* wp = (const float4*)&Wcs[o * 268];
            const float4* pp = (const float4*)&pred[tt * 268];
#pragma unroll 11
            for (int q = 0; q < 66; q++) {
                float4 w = wp[q], p = pp[q];
                acc += w.x * p.x + w.y * p.y + w.z * p.z + w.w * p.w;
            }
            out[CONT_BASE + (size_t)gtok * 50 + o] = acc;
        } else if (o < 60) {
            const int o2 = o - 50;
            float acc = bbs[o2];
            const float4* wp = (const float4*)&Wbs[o2 * 268];
            const float4* pp = (const float4*)&pred[tt * 268];
#pragma unroll 11
            for (int q = 0; q < 66; q++) {
                float4 w = wp[q], p = pp[q];
                acc += w.x * p.x + w.y * p.y + w.z * p.z + w.w * p.w;
            }
            out[BIN_BASE + (size_t)gtok * 10 + o2] = 1.0f / (1.0f + __expf(-acc));
        } else {
            const int o3 = o - 60;
            float acc = bas[o3];
            const float4* wp = (const float4*)&Was[o3 * 256];
            const float4* pp = (const float4*)&a1s[tt * 256];
#pragma unroll 16
            for (int q = 0; q < 64; q++) {
                float4 w = wp[q], p = pp[q];
                acc += w.x * p.x + w.y * p.y + w.z * p.z + w.w * p.w;
            }
            out[ACT_BASE + (size_t)gtok * 8 + o3] = acc;
        }
    }
}

// ---------------------------------------------------------------------------
extern "C" void kernel_launch(void* const* d_in, const int* in_sizes, int n_in,
                              void* d_out, int out_size) {
    const float* x    = (const float*)d_in[0];
    const float* Wih  = (const float*)d_in[1];
    const float* Whh  = (const float*)d_in[2];
    const float* bih  = (const float*)d_in[3];
    const float* bhh  = (const float*)d_in[4];
    const float* Wafc = (const float*)d_in[5];
    const float* bafc = (const float*)d_in[6];
    const float* Wao  = (const float*)d_in[7];
    const float* bao  = (const float*)d_in[8];
    const float* Wc   = (const float*)d_in[9];
    const float* bc   = (const float*)d_in[10];
    const float* Wb   = (const float*)d_in[11];
    const float* bb   = (const float*)d_in[12];
    float* out = (float*)d_out;

    cudaFuncSetAttribute(kB,  cudaFuncAttributeMaxDynamicSharedMemorySize, SMEM_B);
    cudaFuncSetAttribute(kC1, cudaFuncAttributeMaxDynamicSharedMemorySize, SMEM_C1);
    cudaFuncSetAttribute(kC2, cudaFuncAttributeMaxDynamicSharedMemorySize, SMEM_C2);

    k_init<<<1, 32>>>();
    kA<<<dim3(4, 32, 128), 256>>>(x, Wih, bih, bhh);
    kB<<<128, 512, SMEM_B>>>(Whh);
    kC1<<<4096, 256, SMEM_C1>>>(Wafc, bafc);
    kC2<<<4096, 256, SMEM_C2>>>(x, Wao, bao, Wc, bc, Wb, bb, out);
}